// round 3
// baseline (speedup 1.0000x reference)
#include <cuda_runtime.h>
#include <cstdint>

#define NN 100000
#define EE 1600000
#define HID 128
#define INDIM 16
#define LN_EPS 1e-5f

typedef unsigned long long ull;

// ------------------------- device scratch (no allocs allowed) ---------------
__device__ int   g_deg[NN];
__device__ int   g_cursor[NN];
__device__ int   g_rowptr[NN + 1];
__device__ int   g_esrc[EE];
__device__ float g_dis[NN];
__device__ float g_hs[NN * HID];   // dis[n] * h[n]  (gather operand)
__device__ float g_h[NN * HID];    // h (residual operand)
__device__ float g_agg[NN * HID];

// ------------------------- f32x2 helpers ------------------------------------
__device__ __forceinline__ ull pk2(float x, float y) {
    ull r;
    asm("mov.b64 %0, {%1, %2};" : "=l"(r) : "f"(x), "f"(y));
    return r;
}
__device__ __forceinline__ ull ffma2(ull a, ull b, ull c) {
    ull d;
    asm("fma.rn.f32x2 %0, %1, %2, %3;" : "=l"(d) : "l"(a), "l"(b), "l"(c));
    return d;
}
__device__ __forceinline__ float2 upk2(ull a) {
    float2 f;
    asm("mov.b64 {%0, %1}, %2;" : "=f"(f.x), "=f"(f.y) : "l"(a));
    return f;
}

// ------------------------- graph preprocessing -------------------------------
__global__ void count_deg_k(const int* __restrict__ ei) {
    int i = blockIdx.x * blockDim.x + threadIdx.x;
    if (i < EE / 4) {
        int4 d = ((const int4*)(ei + EE))[i];
        atomicAdd(&g_deg[d.x], 1);
        atomicAdd(&g_deg[d.y], 1);
        atomicAdd(&g_deg[d.z], 1);
        atomicAdd(&g_deg[d.w], 1);
    }
}

// exclusive scan of g_deg -> g_rowptr (+cursor copy, +dis), single block 1024
__global__ void scan_k() {
    __shared__ int ssum[1024];
    int t = threadIdx.x;
    const int per = (NN + 1023) / 1024;
    int start = t * per;
    int end = start + per;
    if (start > NN) start = NN;
    if (end > NN) end = NN;
    int s = 0;
    for (int i = start; i < end; i++) s += g_deg[i];
    ssum[t] = s;
    __syncthreads();
    for (int d = 1; d < 1024; d <<= 1) {
        int v = (t >= d) ? ssum[t - d] : 0;
        __syncthreads();
        ssum[t] += v;
        __syncthreads();
    }
    int off = ssum[t] - s;
    for (int i = start; i < end; i++) {
        g_rowptr[i] = off;
        g_cursor[i] = off;
        g_dis[i] = rsqrtf((float)(g_deg[i] + 1));  // +1 self loop
        off += g_deg[i];
    }
    if (t == 1023) g_rowptr[NN] = off;
}

__global__ void build_csr_k(const int* __restrict__ ei) {
    int i = blockIdx.x * blockDim.x + threadIdx.x;
    if (i >= EE / 4) return;
    int4 s = ((const int4*)ei)[i];
    int4 d = ((const int4*)(ei + EE))[i];
    g_esrc[atomicAdd(&g_cursor[d.x], 1)] = s.x;
    g_esrc[atomicAdd(&g_cursor[d.y], 1)] = s.y;
    g_esrc[atomicAdd(&g_cursor[d.z], 1)] = s.z;
    g_esrc[atomicAdd(&g_cursor[d.w], 1)] = s.w;
}

// ------------------------- input projection: hs0 = dis * (x @ W_in + b_in) ---
__global__ void in_proj_k(const float* __restrict__ x,
                          const float* __restrict__ Win,
                          const float* __restrict__ bin) {
    __shared__ float sW[INDIM * HID];
    int tid = threadIdx.x;
    for (int i = tid; i < INDIM * HID / 4; i += blockDim.x)
        ((float4*)sW)[i] = ((const float4*)Win)[i];
    __syncthreads();
    int gidx = blockIdx.x * blockDim.x + tid;
    int row  = gidx >> 5;
    int lane = gidx & 31;
    if (row >= NN) return;
    int c0 = lane * 4;
    float4 b = ((const float4*)bin)[lane];
    float a0 = b.x, a1 = b.y, a2 = b.z, a3 = b.w;
    const float* xr = x + row * INDIM;
#pragma unroll
    for (int k = 0; k < INDIM; k++) {
        float xv = __ldg(xr + k);
        float4 w = *(const float4*)&sW[k * HID + c0];
        a0 += xv * w.x; a1 += xv * w.y; a2 += xv * w.z; a3 += xv * w.w;
    }
    float dn = g_dis[row];
    float4 o = make_float4(dn * a0, dn * a1, dn * a2, dn * a3);
    *(float4*)&g_hs[row * HID + c0] = o;
}

// ------------------------- per-layer aggregation (CSR gather) ----------------
// agg[n] = dis[n] * ( hs[n] + sum_e hs[src_e] ),  warp per node, float4/lane
__global__ void aggregate_k() {
    int n    = (blockIdx.x * blockDim.x + threadIdx.x) >> 5;
    int lane = threadIdx.x & 31;
    if (n >= NN) return;
    const float4* hp = (const float4*)g_hs;
    float dn = g_dis[n];
    float4 a0 = hp[n * 32 + lane];  // self-loop term (already dis-scaled)
    float4 a1 = make_float4(0.f, 0.f, 0.f, 0.f);
    float4 a2 = make_float4(0.f, 0.f, 0.f, 0.f);
    float4 a3 = make_float4(0.f, 0.f, 0.f, 0.f);
    int j = g_rowptr[n], end = g_rowptr[n + 1];
    for (; j + 3 < end; j += 4) {
        int s0 = g_esrc[j], s1 = g_esrc[j + 1];
        int s2 = g_esrc[j + 2], s3 = g_esrc[j + 3];
        float4 v0 = hp[s0 * 32 + lane];
        float4 v1 = hp[s1 * 32 + lane];
        float4 v2 = hp[s2 * 32 + lane];
        float4 v3 = hp[s3 * 32 + lane];
        a0.x += v0.x; a0.y += v0.y; a0.z += v0.z; a0.w += v0.w;
        a1.x += v1.x; a1.y += v1.y; a1.z += v1.z; a1.w += v1.w;
        a2.x += v2.x; a2.y += v2.y; a2.z += v2.z; a2.w += v2.w;
        a3.x += v3.x; a3.y += v3.y; a3.z += v3.z; a3.w += v3.w;
    }
    for (; j < end; j++) {
        int s0 = g_esrc[j];
        float4 v0 = hp[s0 * 32 + lane];
        a0.x += v0.x; a0.y += v0.y; a0.z += v0.z; a0.w += v0.w;
    }
    float4 o = make_float4(dn * (a0.x + a1.x + a2.x + a3.x),
                           dn * (a0.y + a1.y + a2.y + a3.y),
                           dn * (a0.z + a1.z + a2.z + a3.z),
                           dn * (a0.w + a1.w + a2.w + a3.w));
    ((float4*)g_agg)[n * 32 + lane] = o;
}

// ------------------------- fused GEMM + bias + LN + ReLU + residual ----------
// 64 rows/block, 8 warps, 8 rows/warp (as 4 row-pairs), 4 cols/lane.
// A-tile stored transposed (sAt[k][r], stride 66) so row-pairs load as packed
// f32x2 via LDS.64; only W needs lane-local duplication.
#define SAT_STRIDE 66
#define SMEM_FLOATS (16384 + 128 * SAT_STRIDE)

__global__ __launch_bounds__(256, 2) void gemm_ln_k(
    const float* __restrict__ Wc, const float* __restrict__ bc,
    const float* __restrict__ gamma, const float* __restrict__ beta,
    float* __restrict__ out_h, int do_res, int write_hs) {
    extern __shared__ float smem[];
    float* sW  = smem;           // 128*128
    float* sAt = smem + 16384;   // [128][66] transposed tile
    int tid  = threadIdx.x;
    int row0 = blockIdx.x * 64;

    for (int i = tid; i < 4096; i += 256)
        ((float4*)sW)[i] = ((const float4*)Wc)[i];
    {
        const float4* Ag = (const float4*)g_agg;
        for (int i = tid; i < 2048; i += 256) {
            int r = i >> 5, ci = i & 31;
            float4 v = (row0 + r < NN) ? Ag[row0 * 32 + i]
                                       : make_float4(0.f, 0.f, 0.f, 0.f);
            int c0 = ci * 4;
            sAt[(c0 + 0) * SAT_STRIDE + r] = v.x;
            sAt[(c0 + 1) * SAT_STRIDE + r] = v.y;
            sAt[(c0 + 2) * SAT_STRIDE + r] = v.z;
            sAt[(c0 + 3) * SAT_STRIDE + r] = v.w;
        }
    }
    __syncthreads();

    int warp = tid >> 5, lane = tid & 31;
    int rb = warp * 8;
    int c0 = lane * 4;
    ull acc[4][4];
#pragma unroll
    for (int p = 0; p < 4; p++)
#pragma unroll
        for (int c = 0; c < 4; c++) acc[p][c] = 0ull;

#pragma unroll 4
    for (int k = 0; k < 128; k++) {
        float4 w = *(const float4*)&sW[k * 128 + c0];
        ull w0 = pk2(w.x, w.x), w1 = pk2(w.y, w.y);
        ull w2 = pk2(w.z, w.z), w3 = pk2(w.w, w.w);
        const ull* ap = (const ull*)&sAt[k * SAT_STRIDE + rb];
        ull a0 = ap[0], a1 = ap[1], a2 = ap[2], a3 = ap[3];
        acc[0][0] = ffma2(a0, w0, acc[0][0]);
        acc[0][1] = ffma2(a0, w1, acc[0][1]);
        acc[0][2] = ffma2(a0, w2, acc[0][2]);
        acc[0][3] = ffma2(a0, w3, acc[0][3]);
        acc[1][0] = ffma2(a1, w0, acc[1][0]);
        acc[1][1] = ffma2(a1, w1, acc[1][1]);
        acc[1][2] = ffma2(a1, w2, acc[1][2]);
        acc[1][3] = ffma2(a1, w3, acc[1][3]);
        acc[2][0] = ffma2(a2, w0, acc[2][0]);
        acc[2][1] = ffma2(a2, w1, acc[2][1]);
        acc[2][2] = ffma2(a2, w2, acc[2][2]);
        acc[2][3] = ffma2(a2, w3, acc[2][3]);
        acc[3][0] = ffma2(a3, w0, acc[3][0]);
        acc[3][1] = ffma2(a3, w1, acc[3][1]);
        acc[3][2] = ffma2(a3, w2, acc[3][2]);
        acc[3][3] = ffma2(a3, w3, acc[3][3]);
    }

    float4 bv  = ((const float4*)bc)[lane];
    float4 gv  = ((const float4*)gamma)[lane];
    float4 btv = ((const float4*)beta)[lane];

#pragma unroll
    for (int r = 0; r < 8; r++) {
        int row = row0 + rb + r;
        if (row >= NN) continue;
        int p = r >> 1;
        bool hi = r & 1;
        float2 u0 = upk2(acc[p][0]);
        float2 u1 = upk2(acc[p][1]);
        float2 u2 = upk2(acc[p][2]);
        float2 u3 = upk2(acc[p][3]);
        float o0 = (hi ? u0.y : u0.x) + bv.x;
        float o1 = (hi ? u1.y : u1.x) + bv.y;
        float o2 = (hi ? u2.y : u2.x) + bv.z;
        float o3 = (hi ? u3.y : u3.x) + bv.w;
        float s = o0 + o1 + o2 + o3;
#pragma unroll
        for (int d = 16; d; d >>= 1) s += __shfl_xor_sync(0xffffffffu, s, d);
        float mean = s * (1.0f / 128.0f);
        float d0 = o0 - mean, d1 = o1 - mean, d2 = o2 - mean, d3 = o3 - mean;
        float q = d0 * d0 + d1 * d1 + d2 * d2 + d3 * d3;
#pragma unroll
        for (int d = 16; d; d >>= 1) q += __shfl_xor_sync(0xffffffffu, q, d);
        float rinv = rsqrtf(q * (1.0f / 128.0f) + LN_EPS);
        float v0 = fmaxf(d0 * rinv * gv.x + btv.x, 0.f);
        float v1 = fmaxf(d1 * rinv * gv.y + btv.y, 0.f);
        float v2 = fmaxf(d2 * rinv * gv.z + btv.z, 0.f);
        float v3 = fmaxf(d3 * rinv * gv.w + btv.w, 0.f);
        if (do_res) {
            float4 hp = ((const float4*)g_h)[row * 32 + lane];
            v0 += hp.x; v1 += hp.y; v2 += hp.z; v3 += hp.w;
        }
        float4 o = make_float4(v0, v1, v2, v3);
        ((float4*)out_h)[row * 32 + lane] = o;
        if (write_hs) {
            if (out_h != g_h)  // keep residual buffer up to date
                ((float4*)g_h)[row * 32 + lane] = o;
            float dn = g_dis[row];
            float4 hsv = make_float4(dn * v0, dn * v1, dn * v2, dn * v3);
            ((float4*)g_hs)[row * 32 + lane] = hsv;
        }
    }
}

// ------------------------- host launch ---------------------------------------
extern "C" void kernel_launch(void* const* d_in, const int* in_sizes, int n_in,
                              void* d_out, int out_size) {
    const float* x     = (const float*)d_in[0];
    const int*   ei    = (const int*)d_in[1];   // jax default: int32
    const float* Win   = (const float*)d_in[2];
    const float* bin   = (const float*)d_in[3];
    const float* Wconv = (const float*)d_in[4];
    const float* bconv = (const float*)d_in[5];
    const float* gamma = (const float*)d_in[6];
    const float* beta  = (const float*)d_in[7];
    float* out = (float*)d_out;

    (void)in_sizes; (void)n_in; (void)out_size;

    cudaFuncSetAttribute(gemm_ln_k, cudaFuncAttributeMaxDynamicSharedMemorySize,
                         SMEM_FLOATS * (int)sizeof(float));

    void* degp;
    void* hp;
    cudaGetSymbolAddress(&degp, g_deg);
    cudaGetSymbolAddress(&hp, g_h);
    float* hbase = (float*)hp;

    // stream items (ncu -s 5 -c 1 profiles the 6th): memset(1), count(2),
    // scan(3), build(4), in_proj(5), aggregate(6) <- profiled
    cudaMemsetAsync(degp, 0, NN * sizeof(int));
    count_deg_k<<<(EE / 4 + 255) / 256, 256>>>(ei);
    scan_k<<<1, 1024>>>();
    build_csr_k<<<(EE / 4 + 255) / 256, 256>>>(ei);
    in_proj_k<<<(NN * 32 + 255) / 256, 256>>>(x, Win, bin);

    for (int l = 0; l < 3; l++) {
        aggregate_k<<<(NN * 32 + 255) / 256, 256>>>();
        float* dst = (l == 2) ? out : hbase;
        gemm_ln_k<<<(NN + 63) / 64, 256, SMEM_FLOATS * sizeof(float)>>>(
            Wconv + (size_t)l * HID * HID, bconv + l * HID,
            gamma + l * HID, beta + l * HID, dst, l > 0, l < 2);
    }
}